// round 1
// baseline (speedup 1.0000x reference)
#include <cuda_runtime.h>
#include <cuda_bf16.h>

// Problem constants (fixed by the dataset instance)
#define BB 8
#define CC_TOT 32
#define HH 256
#define WW 512
#define WR 2048
#define DD 48
#define CCHUNK 4                 // channels staged in smem per iteration
#define PADF 48                  // zero pad (floats) at left of each smem row
#define ROWF (PADF + WR)         // 2096 floats per smem row
#define ROWF4 (ROWF / 4)         // 524 float4 per smem row

// cost[b,d,h,w] = sum_c | L[b,c,h,w] - R[b,c,h,4w-d] |, R col<0 treated as 0.
__global__ __launch_bounds__(512, 1)
void build_volume2d_kernel(const float* __restrict__ L,
                           const float* __restrict__ R,
                           float* __restrict__ out) {
    __shared__ float smem[CCHUNK * ROWF];   // 4 * 2096 * 4B = 33536 B (static, <48KB)
    float4* s4 = reinterpret_cast<float4*>(smem);

    const int w = threadIdx.x;      // 0..511
    const int h = blockIdx.x;       // 0..255
    const int b = blockIdx.y;       // 0..7

    // Zero the 48-float left pad of each smem row (covers R columns < 0).
    for (int i = threadIdx.x; i < CCHUNK * (PADF / 4); i += blockDim.x) {
        int row = i / (PADF / 4);
        int k   = i % (PADF / 4);
        s4[row * ROWF4 + k] = make_float4(0.f, 0.f, 0.f, 0.f);
    }

    float acc[DD];
#pragma unroll
    for (int d = 0; d < DD; d++) acc[d] = 0.f;

    const float* Lbh = L + ((size_t)b * CC_TOT * HH + h) * WW;   // + c*HH*WW + w
    const float* Rbh = R + ((size_t)b * CC_TOT * HH + h) * WR;   // + c*HH*WR + col

    for (int c0 = 0; c0 < CC_TOT; c0 += CCHUNK) {
        __syncthreads();   // protect pad/previous-chunk reads before overwrite
        // Stage R rows for channels [c0, c0+CCHUNK) into smem (coalesced float4).
        for (int i = threadIdx.x; i < CCHUNK * (WR / 4); i += blockDim.x) {
            int cl   = i >> 9;        // / 512 float4 per row
            int col4 = i & 511;
            float4 v = reinterpret_cast<const float4*>(
                           Rbh + (size_t)(c0 + cl) * HH * WR)[col4];
            s4[cl * ROWF4 + (PADF / 4) + col4] = v;
        }
        __syncthreads();

#pragma unroll
        for (int cl = 0; cl < CCHUNK; cl++) {
            const float lv = __ldg(Lbh + (size_t)(c0 + cl) * HH * WW + w);
            // Thread w needs padded row floats [4w .. 4w+51]  (float4 index w+k).
            const float4* row = s4 + cl * ROWF4 + w;
#pragma unroll
            for (int k = 0; k < 13; k++) {
                float4 v = row[k];
                const int j0 = 4 * k;   // j = padded index - 4w; need j in [1,48]
                if (j0 + 0 >= 1 && j0 + 0 <= 48) acc[48 - (j0 + 0)] += fabsf(lv - v.x);
                if (j0 + 1 >= 1 && j0 + 1 <= 48) acc[48 - (j0 + 1)] += fabsf(lv - v.y);
                if (j0 + 2 >= 1 && j0 + 2 <= 48) acc[48 - (j0 + 2)] += fabsf(lv - v.z);
                if (j0 + 3 >= 1 && j0 + 3 <= 48) acc[48 - (j0 + 3)] += fabsf(lv - v.w);
            }
        }
    }

    // out[b, d, h, w], coalesced across threads for each d.
    const size_t base = (((size_t)b * DD) * HH + h) * WW + w;
#pragma unroll
    for (int d = 0; d < DD; d++) {
        out[base + (size_t)d * HH * WW] = acc[d];
    }
}

extern "C" void kernel_launch(void* const* d_in, const int* in_sizes, int n_in,
                              void* d_out, int out_size) {
    const float* feat_l = (const float*)d_in[0];
    const float* feat_r = (const float*)d_in[1];
    float* out = (float*)d_out;

    dim3 grid(HH, BB);   // one CTA per (h, b) row
    build_volume2d_kernel<<<grid, 512>>>(feat_l, feat_r, out);
}

// round 3
// speedup vs baseline: 1.0246x; 1.0246x over previous
#include <cuda_runtime.h>
#include <cuda_bf16.h>

// Problem constants (fixed by the dataset instance)
#define BB 8
#define CC_TOT 32
#define HH 256
#define WW 512
#define WR 2048
#define DD 48
#define DHALF 24                 // disparities per CTA
#define CCHUNK 4                 // channels staged in smem per iteration
#define PADF 48                  // zero pad (floats) at left of each smem row
#define ROWF (PADF + WR)         // 2096 floats per smem row
#define ROWF4 (ROWF / 4)         // 524 float4 per smem row

// cost[b,d,h,w] = sum_c | L[b,c,h,w] - R[b,c,h,4w-d] |, R col<0 treated as 0.
// smem row: 48 zero floats, then R[col] at float index col+48.
// Thread w, disparity d needs smem float t = 4w + 48 - d, d in [0,48) -> j = t-4w in [1,48].
// Half g covers d in [24g, 24g+24), local a = d - 24g.
//   g=0: j in [25,48] -> float4 idx w+6 .. w+12
//   g=1: j in [ 1,24] -> float4 idx w+0 .. w+6
// Unified: base float4 = w + 6*(1-g), kk in [0,6], lane e:  a = 24 - 4*kk - e,
// valid iff a in [0,24). (kk=0: e=1..3 only; kk=6: e=0 only.) All compile-time.
__global__ __launch_bounds__(512, 2)
void build_volume2d_kernel(const float* __restrict__ L,
                           const float* __restrict__ R,
                           float* __restrict__ out) {
    __shared__ float smem[CCHUNK * ROWF];   // 4 * 2096 * 4B = 33536 B
    float4* s4 = reinterpret_cast<float4*>(smem);

    const int g = blockIdx.x;       // 0: d in [0,24), 1: d in [24,48)
    const int h = blockIdx.y;       // 0..255
    const int b = blockIdx.z;       // 0..7
    const int w = threadIdx.x;      // 0..511
    const int k0 = 6 - 6 * g;       // starting float4 offset within padded row

    // Zero the 48-float left pad of each smem row (covers R columns < 0).
    for (int i = threadIdx.x; i < CCHUNK * (PADF / 4); i += blockDim.x) {
        int row = i / (PADF / 4);
        int k   = i % (PADF / 4);
        s4[row * ROWF4 + k] = make_float4(0.f, 0.f, 0.f, 0.f);
    }

    float acc[DHALF];
#pragma unroll
    for (int a = 0; a < DHALF; a++) acc[a] = 0.f;

    const float* Lbh = L + ((size_t)b * CC_TOT * HH + h) * WW;   // + c*HH*WW + w
    const float* Rbh = R + ((size_t)b * CC_TOT * HH + h) * WR;   // + c*HH*WR + col

    for (int c0 = 0; c0 < CC_TOT; c0 += CCHUNK) {
        __syncthreads();   // protect previous-chunk reads before overwrite
        // Stage R rows for channels [c0, c0+CCHUNK) into smem (coalesced float4).
        for (int i = threadIdx.x; i < CCHUNK * (WR / 4); i += blockDim.x) {
            int cl   = i >> 9;        // / 512 float4 per row
            int col4 = i & 511;
            float4 v = reinterpret_cast<const float4*>(
                           Rbh + (size_t)(c0 + cl) * HH * WR)[col4];
            s4[cl * ROWF4 + (PADF / 4) + col4] = v;
        }
        __syncthreads();

#pragma unroll
        for (int cl = 0; cl < CCHUNK; cl++) {
            const float lv = __ldg(Lbh + (size_t)(c0 + cl) * HH * WW + w);
            const float4* row = s4 + cl * ROWF4 + w + k0;
#pragma unroll
            for (int kk = 0; kk < 7; kk++) {
                float4 v = row[kk];
                const int abase = 24 - 4 * kk;   // a for lane e: abase - e
                if (abase - 0 >= 0 && abase - 0 < DHALF) acc[abase - 0] += fabsf(lv - v.x);
                if (abase - 1 >= 0 && abase - 1 < DHALF) acc[abase - 1] += fabsf(lv - v.y);
                if (abase - 2 >= 0 && abase - 2 < DHALF) acc[abase - 2] += fabsf(lv - v.z);
                if (abase - 3 >= 0 && abase - 3 < DHALF) acc[abase - 3] += fabsf(lv - v.w);
            }
        }
    }

    // out[b, 24g + a, h, w], coalesced across threads for each a.
    const size_t base = (((size_t)b * DD + DHALF * g) * HH + h) * WW + w;
#pragma unroll
    for (int a = 0; a < DHALF; a++) {
        out[base + (size_t)a * HH * WW] = acc[a];
    }
}

extern "C" void kernel_launch(void* const* d_in, const int* in_sizes, int n_in,
                              void* d_out, int out_size) {
    const float* feat_l = (const float*)d_in[0];
    const float* feat_r = (const float*)d_in[1];
    float* out = (float*)d_out;

    dim3 grid(2, HH, BB);   // d-half fastest so twin CTAs share R via L2
    build_volume2d_kernel<<<grid, 512>>>(feat_l, feat_r, out);
}

// round 4
// speedup vs baseline: 1.3465x; 1.3142x over previous
#include <cuda_runtime.h>

// Problem constants (fixed by the dataset instance)
#define BB 8
#define CC_TOT 32
#define HH 256
#define WW 512
#define WR 2048
#define DD 48
#define DHALF 24               // disparities per CTA
#define CPC 2                  // channels per staged buffer
#define NIT (CC_TOT / CPC)     // 16 pipeline iterations
#define TPB 256                // threads (w positions) per CTA
#define NF4 262                // float4 per staged row window
#define ROWL4 264              // padded row stride (float4)

// cost[b,d,h,w] = sum_c | L[b,c,h,w] - R[b,c,h,4w-d] |, R col<0 treated as 0.
//
// Padded float index p = 4w + 48 - d  (pad = 48 zero floats at left).
// Half g (d in [24g,24g+24)): thread w reads padded f4 [w+k0, w+k0+6], k0=6-6g.
// Lane e of f4 kk: a = 24 - 4kk - e (valid iff 0 <= a < 24), d = 24g + a.
// (Mapping verified correct in round 3, rel_err = 0.)
//
// Each CTA handles one (w-tile of 256, d-half, h, b). R window for the tile
// is staged via cp.async, double buffered, 2 channels per buffer.

__device__ __forceinline__ void cp_async16(unsigned dst, const void* src) {
    asm volatile("cp.async.cg.shared.global [%0], [%1], 16;\n"
                 :: "r"(dst), "l"(src));
}

__global__ __launch_bounds__(TPB, 4)
void build_volume2d_kernel(const float* __restrict__ L,
                           const float* __restrict__ R,
                           float* __restrict__ out) {
    __shared__ float4 s4[2][CPC][ROWL4];   // 2*2*264*16 = 16896 B

    const int tid = threadIdx.x;
    const int wt  = blockIdx.x & 1;        // w tile (0 or 1)
    const int g   = blockIdx.x >> 1;       // d half (0 or 1)
    const int h   = blockIdx.y;
    const int b   = blockIdx.z;
    const int w   = wt * TPB + tid;
    const int k0  = 6 - 6 * g;
    const int gf4_0 = wt * TPB + k0;       // global padded-f4 index of local li=0
    const int rcol0 = 4 * gf4_0 - 48;      // R column of local f4 0, element 0
    // local f4 indices < nzero correspond entirely to R columns < 0 (all zero)
    const int nzero = (wt == 0) ? (12 - k0) : 0;

    // One-time zero of the pad f4s. cp.async never writes li < nzero, so these
    // persist across all buffer refills. Disjoint from cp.async targets.
    if (nzero > 0 && tid < 2 * CPC * 12) {
        int bu = tid / (CPC * 12);
        int ch = (tid / 12) % CPC;
        int li = tid % 12;
        if (li < nzero) s4[bu][ch][li] = make_float4(0.f, 0.f, 0.f, 0.f);
    }

    float acc[DHALF];
#pragma unroll
    for (int a = 0; a < DHALF; a++) acc[a] = 0.f;

    const float* Lbh = L + ((size_t)b * CC_TOT * HH + h) * WW;  // + c*HH*WW + w
    const float* Rbh = R + ((size_t)b * CC_TOT * HH + h) * WR;  // + c*HH*WR + col

    // ---- staging: issue cp.async for 2 channels into buffer bu ----
    auto fill = [&](int bu, int c0) {
#pragma unroll
        for (int base = 0; base < NF4; base += TPB) {   // li = tid, tid+256
            int li = base + tid;
            if (li < NF4 && li >= nzero) {
#pragma unroll
                for (int ch = 0; ch < CPC; ++ch) {
                    const float* src =
                        Rbh + (size_t)(c0 + ch) * HH * WR + (rcol0 + 4 * li);
                    cp_async16((unsigned)__cvta_generic_to_shared(&s4[bu][ch][li]),
                               src);
                }
            }
        }
    };

    fill(0, 0);
    asm volatile("cp.async.commit_group;\n" ::: "memory");

    for (int it = 0; it < NIT; ++it) {
        const int bu = it & 1;
        const int c0 = CPC * it;

        if (it + 1 < NIT) {
            fill(bu ^ 1, c0 + CPC);   // prefetch next chunk into other buffer
            asm volatile("cp.async.commit_group;\n" ::: "memory");
            asm volatile("cp.async.wait_group 1;\n" ::: "memory");
        } else {
            asm volatile("cp.async.wait_group 0;\n" ::: "memory");
        }
        __syncthreads();   // buffer bu fully staged, visible to all warps

        // ---- consume buffer bu: channels c0, c0+1 ----
#pragma unroll
        for (int ch = 0; ch < CPC; ++ch) {
            const float lv = __ldg(Lbh + (size_t)(c0 + ch) * HH * WW + w);
            const float4* row = &s4[bu][ch][tid];
#pragma unroll
            for (int kk = 0; kk < 7; kk++) {
                float4 v = row[kk];
                const int abase = 24 - 4 * kk;   // a for lane e: abase - e
                if (abase - 0 >= 0 && abase - 0 < DHALF) acc[abase - 0] += fabsf(lv - v.x);
                if (abase - 1 >= 0 && abase - 1 < DHALF) acc[abase - 1] += fabsf(lv - v.y);
                if (abase - 2 >= 0 && abase - 2 < DHALF) acc[abase - 2] += fabsf(lv - v.z);
                if (abase - 3 >= 0 && abase - 3 < DHALF) acc[abase - 3] += fabsf(lv - v.w);
            }
        }
        __syncthreads();   // all warps done with bu before it is refilled
    }

    // out[b, 24g + a, h, w], coalesced across threads for each a.
    const size_t base = (((size_t)b * DD + DHALF * g) * HH + h) * WW + w;
#pragma unroll
    for (int a = 0; a < DHALF; a++) {
        out[base + (size_t)a * HH * WW] = acc[a];
    }
}

extern "C" void kernel_launch(void* const* d_in, const int* in_sizes, int n_in,
                              void* d_out, int out_size) {
    const float* feat_l = (const float*)d_in[0];
    const float* feat_r = (const float*)d_in[1];
    float* out = (float*)d_out;

    dim3 grid(4, HH, BB);   // x = (d-half << 1) | w-tile, adjacent CTAs share R via L2
    build_volume2d_kernel<<<grid, TPB>>>(feat_l, feat_r, out);
}

// round 5
// speedup vs baseline: 1.4159x; 1.0515x over previous
#include <cuda_runtime.h>

// Problem constants (fixed by the dataset instance)
#define BB 8
#define CC_TOT 32
#define HH 256
#define WW 512
#define WR 2048
#define DD 48
#define DHALF 24               // disparities per CTA
#define CPC 2                  // channels per staged buffer
#define NIT (CC_TOT / CPC)     // 16 pipeline iterations
#define TPB 128                // threads per CTA; each owns 2 adjacent pixels
#define WTILE 256              // w positions per CTA
#define NF4T 262               // staged f4 per channel row window
#define ROWL4 264              // row stride (f4)
#define SWZ(i) ((i) ^ (((i) >> 3) & 1))   // bank-conflict swizzle on f4 index

// cost[b,d,h,w] = sum_c | L[b,c,h,w] - R[b,c,h,4w-d] |, R col<0 treated as 0.
// Padded float index p = 4w + 48 - d. Half g: pixel w reads padded f4
// [w+k0, w+k0+6], k0 = 6-6g; lane e of f4 kk -> a = 24-4kk-e  (R3-verified).
// Thread owns pixels w0=wbase+2*tid and w0+1: union window f4 lb+j, j=0..7,
// lb=2*tid (local). pixel0: a=24-4j-e; pixel1: a1=28-4j-e; valid iff in [0,24).

__device__ __forceinline__ void cp_async16(unsigned dst, const void* src) {
    asm volatile("cp.async.cg.shared.global [%0], [%1], 16;\n"
                 :: "r"(dst), "l"(src));
}

__global__ __launch_bounds__(TPB, 4)
void build_volume2d_kernel(const float* __restrict__ L,
                           const float* __restrict__ R,
                           float* __restrict__ out) {
    __shared__ float4 s4[2][CPC][ROWL4];   // 2*2*264*16 = 16896 B

    const int tid = threadIdx.x;
    const int g   = blockIdx.x & 1;        // d half
    const int wt  = blockIdx.x >> 1;       // w tile (0 or 1)
    const int h   = blockIdx.y;
    const int b   = blockIdx.z;
    const int k0  = 6 - 6 * g;
    const int wbase = wt * WTILE;
    const int w0  = wbase + 2 * tid;
    const int g4s = wbase + k0;            // global padded-f4 index of local li=0
    const int rcol0 = 4 * g4s - 48;        // R column of local f4 0, element 0
    // local f4 li < nzero lie entirely in the zero pad (R col < 0)
    const int nzero = (wt == 0) ? (12 - k0) : 0;   // g=0 -> 6, g=1 -> 12

    // One-time zero of pad f4s (never touched by cp.async; disjoint addresses).
    if (tid < 2 * CPC * 12) {
        int bu = tid / (CPC * 12);
        int ch = (tid / 12) % CPC;
        int li = tid % 12;
        if (li < nzero) s4[bu][ch][SWZ(li)] = make_float4(0.f, 0.f, 0.f, 0.f);
    }

    // Precompute swizzled read indices for this thread's 8-f4 window.
    int idx[8];
#pragma unroll
    for (int j = 0; j < 8; j++) idx[j] = SWZ(2 * tid + j);

    float acc0[DHALF], acc1[DHALF];
#pragma unroll
    for (int a = 0; a < DHALF; a++) { acc0[a] = 0.f; acc1[a] = 0.f; }

    const float* Lbh = L + ((size_t)b * CC_TOT * HH + h) * WW;  // + c*HH*WW + w
    const float* Rbh = R + ((size_t)b * CC_TOT * HH + h) * WR;  // + c*HH*WR + col

    auto fill = [&](int bu, int c0) {
#pragma unroll
        for (int base = 0; base < NF4T; base += TPB) {   // li = tid, +128, +256
            int li = base + tid;
            if (li < NF4T && li >= nzero) {
#pragma unroll
                for (int ch = 0; ch < CPC; ++ch) {
                    const float* src =
                        Rbh + (size_t)(c0 + ch) * HH * WR + (rcol0 + 4 * li);
                    cp_async16((unsigned)__cvta_generic_to_shared(
                                   &s4[bu][ch][SWZ(li)]), src);
                }
            }
        }
    };

    fill(0, 0);
    asm volatile("cp.async.commit_group;\n" ::: "memory");

    for (int it = 0; it < NIT; ++it) {
        const int bu = it & 1;
        const int c0 = CPC * it;

        if (it + 1 < NIT) {
            fill(bu ^ 1, c0 + CPC);
            asm volatile("cp.async.commit_group;\n" ::: "memory");
            asm volatile("cp.async.wait_group 1;\n" ::: "memory");
        } else {
            asm volatile("cp.async.wait_group 0;\n" ::: "memory");
        }
        __syncthreads();   // buffer bu staged & pad stores visible

#pragma unroll
        for (int ch = 0; ch < CPC; ++ch) {
            const float2 lp = *reinterpret_cast<const float2*>(
                Lbh + (size_t)(c0 + ch) * HH * WW + w0);
            const float lv0 = lp.x, lv1 = lp.y;
            const float4* row = s4[bu][ch];
#pragma unroll
            for (int j = 0; j < 8; j++) {
                float4 v = row[idx[j]];
                const float ve[4] = {v.x, v.y, v.z, v.w};
#pragma unroll
                for (int e = 0; e < 4; e++) {
                    const int a  = 24 - 4 * j - e;   // pixel w0
                    const int a1 = 28 - 4 * j - e;   // pixel w0+1
                    if (a  >= 0 && a  < DHALF) acc0[a]  += fabsf(lv0 - ve[e]);
                    if (a1 >= 0 && a1 < DHALF) acc1[a1] += fabsf(lv1 - ve[e]);
                }
            }
        }
        __syncthreads();   // all warps done with bu before refill
    }

    // out[b, 24g + a, h, w0..w0+1] as float2 (coalesced per a).
    const size_t obase = (((size_t)b * DD + DHALF * g) * HH + h) * WW + w0;
#pragma unroll
    for (int a = 0; a < DHALF; a++) {
        *reinterpret_cast<float2*>(&out[obase + (size_t)a * HH * WW]) =
            make_float2(acc0[a], acc1[a]);
    }
}

extern "C" void kernel_launch(void* const* d_in, const int* in_sizes, int n_in,
                              void* d_out, int out_size) {
    const float* feat_l = (const float*)d_in[0];
    const float* feat_r = (const float*)d_in[1];
    float* out = (float*)d_out;

    dim3 grid(4, HH, BB);   // x = (wt<<1)|g : twin-g CTAs share R rows via L2
    build_volume2d_kernel<<<grid, TPB>>>(feat_l, feat_r, out);
}

// round 6
// speedup vs baseline: 1.6095x; 1.1367x over previous
#include <cuda_runtime.h>

// Problem constants (fixed by the dataset instance)
#define BB 8
#define CC_TOT 32
#define HH 256
#define WW 512
#define WR 2048
#define DD 48
#define DHALF 24               // disparities per CTA
#define CPC 2                  // channels per staged buffer
#define NIT (CC_TOT / CPC)     // 16 pipeline iterations
#define TPB 128                // threads per CTA; each owns 2 adjacent pixels
#define WTILE 256              // w positions per CTA
#define NF4T 262               // staged f4 per channel row window
#define ROWL4 264              // row stride (f4)
#define SWZ(i) ((i) ^ (((i) >> 3) & 1))   // bank-conflict swizzle on f4 index

// cost[b,d,h,w] = sum_c | L[b,c,h,w] - R[b,c,h,4w-d] |, R col<0 treated as 0.
// Padded float index p = 4w + 48 - d. Half g: pixel w reads padded f4
// [w+k0, w+k0+6], k0 = 6-6g; lane e of f4 kk -> a = 24-4kk-e  (R3-verified).
// Thread owns pixels w0=wbase+2*tid and w0+1: union window f4 lb+j, j=0..7,
// lb=2*tid (local). pixel0: a=24-4j-e; pixel1: a1=28-4j-e; valid iff in [0,24).
// (R5-verified.) R6 adds register software-pipelining of the L loads.

__device__ __forceinline__ void cp_async16(unsigned dst, const void* src) {
    asm volatile("cp.async.cg.shared.global [%0], [%1], 16;\n"
                 :: "r"(dst), "l"(src));
}

__global__ __launch_bounds__(TPB, 4)
void build_volume2d_kernel(const float* __restrict__ L,
                           const float* __restrict__ R,
                           float* __restrict__ out) {
    __shared__ float4 s4[2][CPC][ROWL4];   // 2*2*264*16 = 16896 B

    const int tid = threadIdx.x;
    const int g   = blockIdx.x & 1;        // d half
    const int wt  = blockIdx.x >> 1;       // w tile (0 or 1)
    const int h   = blockIdx.y;
    const int b   = blockIdx.z;
    const int k0  = 6 - 6 * g;
    const int wbase = wt * WTILE;
    const int w0  = wbase + 2 * tid;
    const int g4s = wbase + k0;            // global padded-f4 index of local li=0
    const int rcol0 = 4 * g4s - 48;        // R column of local f4 0, element 0
    // local f4 li < nzero lie entirely in the zero pad (R col < 0)
    const int nzero = (wt == 0) ? (12 - k0) : 0;   // g=0 -> 6, g=1 -> 12

    // One-time zero of pad f4s (never touched by cp.async; disjoint addresses).
    if (tid < 2 * CPC * 12) {
        int bu = tid / (CPC * 12);
        int ch = (tid / 12) % CPC;
        int li = tid % 12;
        if (li < nzero) s4[bu][ch][SWZ(li)] = make_float4(0.f, 0.f, 0.f, 0.f);
    }

    // Precompute swizzled read indices for this thread's 8-f4 window.
    int idx[8];
#pragma unroll
    for (int j = 0; j < 8; j++) idx[j] = SWZ(2 * tid + j);

    float acc0[DHALF], acc1[DHALF];
#pragma unroll
    for (int a = 0; a < DHALF; a++) { acc0[a] = 0.f; acc1[a] = 0.f; }

    const float* Lbh = L + ((size_t)b * CC_TOT * HH + h) * WW + w0;  // + c*HH*WW
    const float* Rbh = R + ((size_t)b * CC_TOT * HH + h) * WR;       // + c*HH*WR

    auto fill = [&](int bu, int c0) {
#pragma unroll
        for (int base = 0; base < NF4T; base += TPB) {   // li = tid, +128, +256
            int li = base + tid;
            if (li < NF4T && li >= nzero) {
#pragma unroll
                for (int ch = 0; ch < CPC; ++ch) {
                    const float* src =
                        Rbh + (size_t)(c0 + ch) * HH * WR + (rcol0 + 4 * li);
                    cp_async16((unsigned)__cvta_generic_to_shared(
                                   &s4[bu][ch][SWZ(li)]), src);
                }
            }
        }
    };

    fill(0, 0);
    asm volatile("cp.async.commit_group;\n" ::: "memory");

    // Preload L for iteration 0 (overlaps with cp.async of buffer 0).
    float2 lp[CPC];
#pragma unroll
    for (int ch = 0; ch < CPC; ++ch)
        lp[ch] = __ldg(reinterpret_cast<const float2*>(
                           Lbh + (size_t)ch * HH * WW));

    for (int it = 0; it < NIT; ++it) {
        const int bu = it & 1;
        const int c0 = CPC * it;

        // Prefetch next iteration's L into registers (hides LDG latency
        // behind this iteration's FADD block).
        float2 lpn[CPC];
        if (it + 1 < NIT) {
#pragma unroll
            for (int ch = 0; ch < CPC; ++ch)
                lpn[ch] = __ldg(reinterpret_cast<const float2*>(
                                    Lbh + (size_t)(c0 + CPC + ch) * HH * WW));
            fill(bu ^ 1, c0 + CPC);
            asm volatile("cp.async.commit_group;\n" ::: "memory");
            asm volatile("cp.async.wait_group 1;\n" ::: "memory");
        } else {
            asm volatile("cp.async.wait_group 0;\n" ::: "memory");
        }
        __syncthreads();   // buffer bu staged & pad stores visible

#pragma unroll
        for (int ch = 0; ch < CPC; ++ch) {
            const float lv0 = lp[ch].x, lv1 = lp[ch].y;
            const float4* row = s4[bu][ch];
#pragma unroll
            for (int j = 0; j < 8; j++) {
                float4 v = row[idx[j]];
                const float ve[4] = {v.x, v.y, v.z, v.w};
#pragma unroll
                for (int e = 0; e < 4; e++) {
                    const int a  = 24 - 4 * j - e;   // pixel w0
                    const int a1 = 28 - 4 * j - e;   // pixel w0+1
                    if (a  >= 0 && a  < DHALF) acc0[a]  += fabsf(lv0 - ve[e]);
                    if (a1 >= 0 && a1 < DHALF) acc1[a1] += fabsf(lv1 - ve[e]);
                }
            }
        }
#pragma unroll
        for (int ch = 0; ch < CPC; ++ch) lp[ch] = lpn[ch];

        __syncthreads();   // all warps done with bu before refill
    }

    // out[b, 24g + a, h, w0..w0+1] as float2 (coalesced per a).
    const size_t obase = (((size_t)b * DD + DHALF * g) * HH + h) * WW + w0;
#pragma unroll
    for (int a = 0; a < DHALF; a++) {
        *reinterpret_cast<float2*>(&out[obase + (size_t)a * HH * WW]) =
            make_float2(acc0[a], acc1[a]);
    }
}

extern "C" void kernel_launch(void* const* d_in, const int* in_sizes, int n_in,
                              void* d_out, int out_size) {
    const float* feat_l = (const float*)d_in[0];
    const float* feat_r = (const float*)d_in[1];
    float* out = (float*)d_out;

    dim3 grid(4, HH, BB);   // x = (wt<<1)|g : twin-g CTAs share R rows via L2
    build_volume2d_kernel<<<grid, TPB>>>(feat_l, feat_r, out);
}

// round 7
// speedup vs baseline: 1.6470x; 1.0233x over previous
#include <cuda_runtime.h>

// Problem constants (fixed by the dataset instance)
#define BB 8
#define CC_TOT 32
#define HH 256
#define WW 512
#define WR 2048
#define DD 48
#define DHALF 24               // disparities per CTA
#define CPC 2                  // channels per staged buffer
#define NIT (CC_TOT / CPC)     // 16 pipeline iterations
#define NSTG 3                 // cp.async pipeline stages
#define TPB 128                // threads per CTA; each owns 2 adjacent pixels
#define WTILE 256              // w positions per CTA
#define NF4T 262               // staged f4 per channel row window
#define ROWL4 264              // row stride (f4)
#define SWZ(i) ((i) ^ (((i) >> 3) & 1))   // bank-conflict swizzle on f4 index

// cost[b,d,h,w] = sum_c | L[b,c,h,w] - R[b,c,h,4w-d] |, R col<0 treated as 0.
// Padded float index p = 4w + 48 - d. Half g: pixel w reads padded f4
// [w+k0, w+k0+6], k0 = 6-6g; lane e of f4 kk -> a = 24-4kk-e.
// Thread owns pixels w0=wbase+2*tid, w0+1: union window f4 2*tid+j, j=0..7;
// pixel0: a=24-4j-e; pixel1: a1=28-4j-e; valid iff in [0,24). (R5/R6-verified.)
// R7: diff as FFMA-imm (rt1 vs rt2 FADD), 3-stage pipeline w/ 1 sync/iter,
// L prefetch depth 2.

__device__ __forceinline__ void cp_async16(unsigned dst, const void* src) {
    asm volatile("cp.async.cg.shared.global [%0], [%1], 16;\n"
                 :: "r"(dst), "l"(src));
}
// t = lv - v, emitted as imm-form FFMA (t = v * (-1.0f) + lv), exact.
__device__ __forceinline__ float diff_ffma(float v, float lv) {
    float t;
    asm("fma.rn.f32 %0, %1, 0fBF800000, %2;" : "=f"(t) : "f"(v), "f"(lv));
    return t;
}

__global__ __launch_bounds__(TPB, 4)
void build_volume2d_kernel(const float* __restrict__ L,
                           const float* __restrict__ R,
                           float* __restrict__ out) {
    __shared__ float4 s4[NSTG][CPC][ROWL4];   // 3*2*264*16 = 25344 B

    const int tid = threadIdx.x;
    const int g   = blockIdx.x & 1;        // d half
    const int wt  = blockIdx.x >> 1;       // w tile (0 or 1)
    const int h   = blockIdx.y;
    const int b   = blockIdx.z;
    const int k0  = 6 - 6 * g;
    const int wbase = wt * WTILE;
    const int w0  = wbase + 2 * tid;
    const int g4s = wbase + k0;            // global padded-f4 index of local li=0
    const int rcol0 = 4 * g4s - 48;        // R column of local f4 0, element 0
    // local f4 li < nzero lie entirely in the zero pad (R col < 0)
    const int nzero = (wt == 0) ? (12 - k0) : 0;   // g=0 -> 6, g=1 -> 12

    // One-time zero of pad f4s (never touched by cp.async; disjoint addresses).
    if (tid < NSTG * CPC * 12) {
        int st = tid / (CPC * 12);
        int ch = (tid / 12) % CPC;
        int li = tid % 12;
        if (li < nzero) s4[st][ch][SWZ(li)] = make_float4(0.f, 0.f, 0.f, 0.f);
    }

    // Precompute swizzled read indices for this thread's 8-f4 window.
    int idx[8];
#pragma unroll
    for (int j = 0; j < 8; j++) idx[j] = SWZ(2 * tid + j);

    float acc0[DHALF], acc1[DHALF];
#pragma unroll
    for (int a = 0; a < DHALF; a++) { acc0[a] = 0.f; acc1[a] = 0.f; }

    const float* Lbh = L + ((size_t)b * CC_TOT * HH + h) * WW + w0;  // + c*HH*WW
    const float* Rbh = R + ((size_t)b * CC_TOT * HH + h) * WR;       // + c*HH*WR

    auto fill = [&](int st, int c0) {
#pragma unroll
        for (int base = 0; base < NF4T; base += TPB) {   // li = tid, +128, +256
            int li = base + tid;
            if (li < NF4T && li >= nzero) {
#pragma unroll
                for (int ch = 0; ch < CPC; ++ch) {
                    const float* src =
                        Rbh + (size_t)(c0 + ch) * HH * WR + (rcol0 + 4 * li);
                    cp_async16((unsigned)__cvta_generic_to_shared(
                                   &s4[st][ch][SWZ(li)]), src);
                }
            }
        }
    };
    auto loadL = [&](int c0, float2* dst) {
#pragma unroll
        for (int ch = 0; ch < CPC; ++ch)
            dst[ch] = __ldg(reinterpret_cast<const float2*>(
                                Lbh + (size_t)(c0 + ch) * HH * WW));
    };

    // Prologue: stage chunks 0 and 1; preload L for chunks 0 and 1.
    fill(0, 0);
    asm volatile("cp.async.commit_group;\n" ::: "memory");
    fill(1, CPC);
    asm volatile("cp.async.commit_group;\n" ::: "memory");
    float2 lp0[CPC], lp1[CPC];
    loadL(0, lp0);
    loadL(CPC, lp1);

    for (int it = 0; it < NIT; ++it) {
        const int st = it % NSTG;
        const int c0 = CPC * it;

        // Group `it` must be complete. Groups issued so far: min(it+2, NIT).
        if (it < NIT - 1) {
            asm volatile("cp.async.wait_group 1;\n" ::: "memory");
        } else {
            asm volatile("cp.async.wait_group 0;\n" ::: "memory");
        }
        __syncthreads();   // slot st visible to all; all warps past consume(it-1)

        // Prefetch chunk it+2 (slot consumed at iteration it-1; safe post-sync).
        float2 lp2[CPC];
        if (it + 2 < NIT) {
            loadL(c0 + 2 * CPC, lp2);
            fill((it + 2) % NSTG, c0 + 2 * CPC);
            asm volatile("cp.async.commit_group;\n" ::: "memory");
        }

#pragma unroll
        for (int ch = 0; ch < CPC; ++ch) {
            const float lv0 = lp0[ch].x, lv1 = lp0[ch].y;
            const float4* row = s4[st][ch];
#pragma unroll
            for (int j = 0; j < 8; j++) {
                float4 v = row[idx[j]];
                const float ve[4] = {v.x, v.y, v.z, v.w};
#pragma unroll
                for (int e = 0; e < 4; e++) {
                    const int a  = 24 - 4 * j - e;   // pixel w0
                    const int a1 = 28 - 4 * j - e;   // pixel w0+1
                    if (a  >= 0 && a  < DHALF) acc0[a]  += fabsf(diff_ffma(ve[e], lv0));
                    if (a1 >= 0 && a1 < DHALF) acc1[a1] += fabsf(diff_ffma(ve[e], lv1));
                }
            }
        }
#pragma unroll
        for (int ch = 0; ch < CPC; ++ch) { lp0[ch] = lp1[ch]; lp1[ch] = lp2[ch]; }
    }

    // out[b, 24g + a, h, w0..w0+1] as float2 (coalesced per a).
    const size_t obase = (((size_t)b * DD + DHALF * g) * HH + h) * WW + w0;
#pragma unroll
    for (int a = 0; a < DHALF; a++) {
        *reinterpret_cast<float2*>(&out[obase + (size_t)a * HH * WW]) =
            make_float2(acc0[a], acc1[a]);
    }
}

extern "C" void kernel_launch(void* const* d_in, const int* in_sizes, int n_in,
                              void* d_out, int out_size) {
    const float* feat_l = (const float*)d_in[0];
    const float* feat_r = (const float*)d_in[1];
    float* out = (float*)d_out;

    dim3 grid(4, HH, BB);   // x = (wt<<1)|g : twin-g CTAs share R rows via L2
    build_volume2d_kernel<<<grid, TPB>>>(feat_l, feat_r, out);
}